// round 4
// baseline (speedup 1.0000x reference)
#include <cuda_runtime.h>
#include <stdint.h>

// ---------------------------------------------------------------------------
// tcnn HashGrid encode: coords [N,3] in [0,1], table [16, 2^19, 2] f32.
// Output [N, 32] f32. Levels 0-4 dense, 5-15 spatial-hashed.
//
// R4: branchless hashed gather. PRIME_x == 1 so the two x-corners of a cell
// hash to {e, e^1} when gx is even -> one aligned LDG.128 covers both.
// Instead of a divergent even/odd branch (R3: serialized both arms), ALWAYS
// load float4 @ (e & ~1) (contains the dx=0 corner for any parity) and add a
// predicated LDG.64 for the dx=1 corner of odd-gx lanes only. Straight-line
// code, 8 loads in flight, no BSSY/BSYNC. Dense levels: repacked 64B cell
// records, quad-lane LDG.128 (1 line per point-level).
// ---------------------------------------------------------------------------

namespace {
constexpr int      NLV    = 16;
constexpr int      NDENSE = 5;
constexpr int      NHASH  = 11;
constexpr unsigned TSZ    = 1u << 19;
constexpr unsigned TMASK  = TSZ - 1u;
constexpr unsigned PRIME2 = 2654435761u;
constexpr unsigned PRIME3 = 805459861u;

constexpr double spow(int l) {
    double v = 1.0;
    for (int i = 0; i < l; ++i) v *= 1.4472692012786865;
    return v;
}
constexpr double scaled(int l) { return 16.0 * spow(l) - 1.0; }
constexpr unsigned resd(int l) {
    double sc = scaled(l);
    unsigned f = (unsigned)sc;
    return f + (((double)f < sc) ? 1u : 0u) + 1u;
}
constexpr unsigned cells_below(int l) {
    unsigned o = 0;
    for (int i = 0; i < l; ++i) o += resd(i) * resd(i) * resd(i);
    return o;
}
constexpr unsigned TOTAL_CELLS = cells_below(NDENSE);
static_assert(resd(0) == 16 && resd(4) == 71, "dense res sanity");
static_assert((unsigned long long)resd(4)*resd(4)*resd(4) <= TSZ, "lvl4 dense");
static_assert((unsigned long long)resd(5)*resd(5)*resd(5) >  TSZ, "lvl5 hashed");
static_assert(TOTAL_CELLS == 532784u, "cell count");
}

__constant__ float    c_scale[NLV] = {
    (float)scaled(0),(float)scaled(1),(float)scaled(2),(float)scaled(3),
    (float)scaled(4),(float)scaled(5),(float)scaled(6),(float)scaled(7),
    (float)scaled(8),(float)scaled(9),(float)scaled(10),(float)scaled(11),
    (float)scaled(12),(float)scaled(13),(float)scaled(14),(float)scaled(15)};
__constant__ unsigned c_res[NDENSE]  = {resd(0),resd(1),resd(2),resd(3),resd(4)};
__constant__ unsigned c_res2[NDENSE] = {resd(0)*resd(0),resd(1)*resd(1),
    resd(2)*resd(2),resd(3)*resd(3),resd(4)*resd(4)};
__constant__ unsigned c_coff[NDENSE] = {cells_below(0),cells_below(1),
    cells_below(2),cells_below(3),cells_below(4)};

__device__ __align__(128) float4 g_cells[(size_t)TOTAL_CELLS * 4];

// --- repack dense levels: cell (gx,gy,gz) -> 4 float4 = 8 corners (64B).
// chunk k: dx=k>>1, dy=k&1; dz=0 in .xy, dz=1 in .zw.
__global__ void hg_repack(const float2* __restrict__ table) {
    unsigned cid = blockIdx.x * blockDim.x + threadIdx.x;
    if (cid >= TOTAL_CELLS) return;

    int l = 0;
    #pragma unroll
    for (int i = 1; i < NDENSE; ++i) if (cid >= c_coff[i]) l = i;
    const unsigned res = c_res[l], res2 = c_res2[l];
    const unsigned local = cid - c_coff[l];
    const unsigned gz  = local / res2;
    const unsigned rem = local - gz * res2;
    const unsigned gy  = rem / res;
    const unsigned gx  = rem - gy * res;

    const unsigned R1  = res - 1u;
    const unsigned cx0 = gx,          cx1 = min(gx + 1u, R1);
    const unsigned cy0 = gy * res,    cy1 = min(gy + 1u, R1) * res;
    const unsigned cz0 = gz * res2,   cz1 = min(gz + 1u, R1) * res2;

    const float2* __restrict__ tbl = table + (size_t)l * (size_t)TSZ;
    float4* dst = &g_cells[(size_t)cid * 4];
    { float2 a = tbl[cx0+cy0+cz0], b = tbl[cx0+cy0+cz1]; dst[0]=make_float4(a.x,a.y,b.x,b.y); }
    { float2 a = tbl[cx0+cy1+cz0], b = tbl[cx0+cy1+cz1]; dst[1]=make_float4(a.x,a.y,b.x,b.y); }
    { float2 a = tbl[cx1+cy0+cz0], b = tbl[cx1+cy0+cz1]; dst[2]=make_float4(a.x,a.y,b.x,b.y); }
    { float2 a = tbl[cx1+cy1+cz0], b = tbl[cx1+cy1+cz1]; dst[3]=make_float4(a.x,a.y,b.x,b.y); }
}

// --- main encode. Block = 512 threads = 16 warps, 32 points per block.
// warps 0..10 : hashed level (warp+5), lane = point.
// warps 11..15: dense level (warp-11), quad-lane cell fetch, 4 subgroups.
__global__ __launch_bounds__(512, 3) void hg_encode(
    const float*  __restrict__ coords,
    const float2* __restrict__ table,
    float*        __restrict__ out,
    int n_points)
{
    __shared__ float s_c[96];         // 32 points x 3 coords
    __shared__ float s_out[32][33];   // [point][feat], padded

    const int tid   = threadIdx.x;
    const int lane  = tid & 31;
    const int warp  = tid >> 5;
    const int pbase = blockIdx.x * 32;

    if (tid < 96) {
        const int g = pbase * 3 + tid;
        s_c[tid] = (g < n_points * 3) ? coords[g] : 0.0f;
    }
    __syncthreads();

    if (warp < NHASH) {
        // ---------------- hashed levels (branchless) ----------------
        const int level = warp + NDENSE;
        const float x = s_c[lane*3+0], y = s_c[lane*3+1], z = s_c[lane*3+2];
        const float sc = c_scale[level];

        const float px = x*sc + 0.5f, py = y*sc + 0.5f, pz = z*sc + 0.5f;
        const float fx = floorf(px), fy = floorf(py), fz = floorf(pz);
        const float wx = px - fx,    wy = py - fy,    wz = pz - fz;
        const unsigned gx = (unsigned)fx, gy = (unsigned)fy, gz = (unsigned)fz;

        const unsigned hy0 = gy * PRIME2, hy1 = hy0 + PRIME2;
        const unsigned hz0 = gz * PRIME3, hz1 = hz0 + PRIME3;
        const bool     odd = (gx & 1u);
        const unsigned gx1 = gx + 1u;

        // j = (dy,dz): 0=(0,0) 1=(0,1) 2=(1,0) 3=(1,1)
        unsigned e0 = (gx ^ hy0 ^ hz0) & TMASK;
        unsigned e1 = (gx ^ hy0 ^ hz1) & TMASK;
        unsigned e2 = (gx ^ hy1 ^ hz0) & TMASK;
        unsigned e3 = (gx ^ hy1 ^ hz1) & TMASK;

        const float2* __restrict__ tbl = table + (size_t)level * (size_t)TSZ;
        const float4* __restrict__ tb4 = reinterpret_cast<const float4*>(tbl);

        // Unconditional paired loads: entry pair {e&~1, e|1}. Contains the
        // dx=0 corner always, and the dx=1 corner too when gx is even.
        const float4 q0 = __ldg(tb4 + (e0 >> 1));
        const float4 q1 = __ldg(tb4 + (e1 >> 1));
        const float4 q2 = __ldg(tb4 + (e2 >> 1));
        const float4 q3 = __ldg(tb4 + (e3 >> 1));

        // Predicated dx=1 loads, active only for odd-gx lanes (no branch).
        const unsigned f0i = (gx1 ^ hy0 ^ hz0) & TMASK;
        const unsigned f1i = (gx1 ^ hy0 ^ hz1) & TMASK;
        const unsigned f2i = (gx1 ^ hy1 ^ hz0) & TMASK;
        const unsigned f3i = (gx1 ^ hy1 ^ hz1) & TMASK;
        const float2 r0 = odd ? __ldg(tbl + f0i) : make_float2(0.f, 0.f);
        const float2 r1 = odd ? __ldg(tbl + f1i) : make_float2(0.f, 0.f);
        const float2 r2 = odd ? __ldg(tbl + f2i) : make_float2(0.f, 0.f);
        const float2 r3 = odd ? __ldg(tbl + f3i) : make_float2(0.f, 0.f);

        // Select corners. lo = entry e (dx=0); pair-other = e^1 (dx=1 iff even).
        const bool h0 = e0 & 1u, h1 = e1 & 1u, h2 = e2 & 1u, h3 = e3 & 1u;
        const float a0x = h0 ? q0.z : q0.x, a0y = h0 ? q0.w : q0.y;
        const float a1x = h1 ? q1.z : q1.x, a1y = h1 ? q1.w : q1.y;
        const float a2x = h2 ? q2.z : q2.x, a2y = h2 ? q2.w : q2.y;
        const float a3x = h3 ? q3.z : q3.x, a3y = h3 ? q3.w : q3.y;
        const float b0x = odd ? r0.x : (h0 ? q0.x : q0.z);
        const float b0y = odd ? r0.y : (h0 ? q0.y : q0.w);
        const float b1x = odd ? r1.x : (h1 ? q1.x : q1.z);
        const float b1y = odd ? r1.y : (h1 ? q1.y : q1.w);
        const float b2x = odd ? r2.x : (h2 ? q2.x : q2.z);
        const float b2y = odd ? r2.y : (h2 ? q2.y : q2.w);
        const float b3x = odd ? r3.x : (h3 ? q3.x : q3.z);
        const float b3y = odd ? r3.y : (h3 ? q3.y : q3.w);

        const float ix = 1.0f - wx, iy = 1.0f - wy, iz = 1.0f - wz;
        const float a00 = ix*iy, a01 = ix*wy, a10 = wx*iy, a11 = wx*wy;
        const float w0 = a00*iz, w1 = a00*wz, w2 = a01*iz, w3 = a01*wz;
        const float w4 = a10*iz, w5 = a10*wz, w6 = a11*iz, w7 = a11*wz;

        float f0 = w0*a0x;  float f1 = w0*a0y;
        f0 += w1*a1x;       f1 += w1*a1y;
        f0 += w2*a2x;       f1 += w2*a2y;
        f0 += w3*a3x;       f1 += w3*a3y;
        f0 += w4*b0x;       f1 += w4*b0y;
        f0 += w5*b1x;       f1 += w5*b1y;
        f0 += w6*b2x;       f1 += w6*b2y;
        f0 += w7*b3x;       f1 += w7*b3y;

        s_out[lane][2*level + 0] = f0;
        s_out[lane][2*level + 1] = f1;
    } else {
        // ---------------- dense levels: quad-lane cell fetch ----------------
        const int level = warp - NHASH;           // 0..4
        const float    sc   = c_scale[level];
        const unsigned res  = c_res[level];
        const unsigned res2 = c_res2[level];
        const unsigned coff = c_coff[level];
        const int q = lane >> 2;                  // 0..7 point-in-subgroup
        const int k = lane & 3;                   // chunk: dx=k>>1, dy=k&1

        #pragma unroll
        for (int it = 0; it < 4; ++it) {
            const int pt = it * 8 + q;            // 0..31
            const float x = s_c[pt*3+0], y = s_c[pt*3+1], z = s_c[pt*3+2];
            const float px = x*sc + 0.5f, py = y*sc + 0.5f, pz = z*sc + 0.5f;
            const float fx = floorf(px), fy = floorf(py), fz = floorf(pz);
            const float wx = px - fx,    wy = py - fy,    wz = pz - fz;
            const unsigned gx = (unsigned)fx, gy = (unsigned)fy, gz = (unsigned)fz;

            const unsigned cell = coff + gx + gy*res + gz*res2;
            const float4 ch = __ldg(&g_cells[(size_t)cell * 4 + k]);  // 4 lanes: 1 line

            const float wdx = (k & 2) ? wx : 1.0f - wx;
            const float wdy = (k & 1) ? wy : 1.0f - wy;
            const float izz = 1.0f - wz;
            const float s   = wdx * wdy;
            float f0 = s * (izz*ch.x + wz*ch.z);
            float f1 = s * (izz*ch.y + wz*ch.w);

            f0 += __shfl_xor_sync(0xffffffffu, f0, 1);
            f1 += __shfl_xor_sync(0xffffffffu, f1, 1);
            f0 += __shfl_xor_sync(0xffffffffu, f0, 2);
            f1 += __shfl_xor_sync(0xffffffffu, f1, 2);

            if (k == 0) {
                s_out[pt][2*level + 0] = f0;
                s_out[pt][2*level + 1] = f1;
            }
        }
    }
    __syncthreads();

    // Coalesced writeback: 512 threads x float2 = 4KB contiguous per block.
    const int pp = tid >> 4;
    const int c  = (tid & 15) * 2;
    const int gp = pbase + pp;
    if (gp < n_points) {
        const float a = s_out[pp][c];
        const float b = s_out[pp][c + 1];
        float2* o = reinterpret_cast<float2*>(out + (size_t)gp * 32 + c);
        *o = make_float2(a, b);
    }
}

extern "C" void kernel_launch(void* const* d_in, const int* in_sizes, int n_in,
                              void* d_out, int out_size) {
    const float*  coords = (const float*)d_in[0];   // [N, 3] f32
    const float2* table  = (const float2*)d_in[1];  // [16, 2^19, 2] f32
    float*        out    = (float*)d_out;           // [N, 32] f32
    const int n_points = in_sizes[0] / 3;

    hg_repack<<<(TOTAL_CELLS + 255) / 256, 256>>>(table);
    const int blocks = (n_points + 31) / 32;
    hg_encode<<<blocks, 512>>>(coords, table, out, n_points);
}

// round 5
// speedup vs baseline: 1.3289x; 1.3289x over previous
#include <cuda_runtime.h>
#include <stdint.h>

// ---------------------------------------------------------------------------
// tcnn HashGrid encode: coords [N,3] in [0,1], table [16, 2^19, 2] f32.
// Output [N, 32] f32. Levels 0-4 dense, 5-15 spatial-hashed.
//
// R5: fix warp-role imbalance. R3 had 5/16 warps doing a tiny dense task and
// then idling at the block barrier while 11 hashed warps gathered -> only
// ~50% of warp slots fed the L1 pipeline. Now: block = 11 warps; every warp
// owns one hashed level (32 points); warps 0..4 additionally fold in one
// dense level (repacked 64B cell records, quad-lane LDG.128 = +17% work).
// __launch_bounds__(352,5) -> 55 warps/SM, all gathering.
// Hashed path = R3's proven divergent even/odd x-pair merge (PRIME_x==1).
// ---------------------------------------------------------------------------

namespace {
constexpr int      NLV    = 16;
constexpr int      NDENSE = 5;
constexpr int      NHASH  = 11;
constexpr unsigned TSZ    = 1u << 19;
constexpr unsigned TMASK  = TSZ - 1u;
constexpr unsigned PRIME2 = 2654435761u;
constexpr unsigned PRIME3 = 805459861u;

constexpr double spow(int l) {
    double v = 1.0;
    for (int i = 0; i < l; ++i) v *= 1.4472692012786865;
    return v;
}
constexpr double scaled(int l) { return 16.0 * spow(l) - 1.0; }
constexpr unsigned resd(int l) {
    double sc = scaled(l);
    unsigned f = (unsigned)sc;
    return f + (((double)f < sc) ? 1u : 0u) + 1u;
}
constexpr unsigned cells_below(int l) {
    unsigned o = 0;
    for (int i = 0; i < l; ++i) o += resd(i) * resd(i) * resd(i);
    return o;
}
constexpr unsigned TOTAL_CELLS = cells_below(NDENSE);
static_assert(resd(0) == 16 && resd(4) == 71, "dense res sanity");
static_assert((unsigned long long)resd(4)*resd(4)*resd(4) <= TSZ, "lvl4 dense");
static_assert((unsigned long long)resd(5)*resd(5)*resd(5) >  TSZ, "lvl5 hashed");
static_assert(TOTAL_CELLS == 532784u, "cell count");
}

__constant__ float    c_scale[NLV] = {
    (float)scaled(0),(float)scaled(1),(float)scaled(2),(float)scaled(3),
    (float)scaled(4),(float)scaled(5),(float)scaled(6),(float)scaled(7),
    (float)scaled(8),(float)scaled(9),(float)scaled(10),(float)scaled(11),
    (float)scaled(12),(float)scaled(13),(float)scaled(14),(float)scaled(15)};
__constant__ unsigned c_res[NDENSE]  = {resd(0),resd(1),resd(2),resd(3),resd(4)};
__constant__ unsigned c_res2[NDENSE] = {resd(0)*resd(0),resd(1)*resd(1),
    resd(2)*resd(2),resd(3)*resd(3),resd(4)*resd(4)};
__constant__ unsigned c_coff[NDENSE] = {cells_below(0),cells_below(1),
    cells_below(2),cells_below(3),cells_below(4)};

__device__ __align__(128) float4 g_cells[(size_t)TOTAL_CELLS * 4];

// --- repack dense levels: cell (gx,gy,gz) -> 4 float4 = 8 corners (64B).
// chunk k: dx=k>>1, dy=k&1; dz=0 in .xy, dz=1 in .zw.
__global__ void hg_repack(const float2* __restrict__ table) {
    unsigned cid = blockIdx.x * blockDim.x + threadIdx.x;
    if (cid >= TOTAL_CELLS) return;

    int l = 0;
    #pragma unroll
    for (int i = 1; i < NDENSE; ++i) if (cid >= c_coff[i]) l = i;
    const unsigned res = c_res[l], res2 = c_res2[l];
    const unsigned local = cid - c_coff[l];
    const unsigned gz  = local / res2;
    const unsigned rem = local - gz * res2;
    const unsigned gy  = rem / res;
    const unsigned gx  = rem - gy * res;

    const unsigned R1  = res - 1u;
    const unsigned cx0 = gx,          cx1 = min(gx + 1u, R1);
    const unsigned cy0 = gy * res,    cy1 = min(gy + 1u, R1) * res;
    const unsigned cz0 = gz * res2,   cz1 = min(gz + 1u, R1) * res2;

    const float2* __restrict__ tbl = table + (size_t)l * (size_t)TSZ;
    float4* dst = &g_cells[(size_t)cid * 4];
    { float2 a = tbl[cx0+cy0+cz0], b = tbl[cx0+cy0+cz1]; dst[0]=make_float4(a.x,a.y,b.x,b.y); }
    { float2 a = tbl[cx0+cy1+cz0], b = tbl[cx0+cy1+cz1]; dst[1]=make_float4(a.x,a.y,b.x,b.y); }
    { float2 a = tbl[cx1+cy0+cz0], b = tbl[cx1+cy0+cz1]; dst[2]=make_float4(a.x,a.y,b.x,b.y); }
    { float2 a = tbl[cx1+cy1+cz0], b = tbl[cx1+cy1+cz1]; dst[3]=make_float4(a.x,a.y,b.x,b.y); }
}

// --- main encode. Block = 352 threads = 11 warps, 32 points per block.
// warp w handles hashed level w+5; warps 0..4 also handle dense level w.
__global__ __launch_bounds__(352, 5) void hg_encode(
    const float*  __restrict__ coords,
    const float2* __restrict__ table,
    float*        __restrict__ out,
    int n_points)
{
    __shared__ float s_c[96];         // 32 points x 3 coords
    __shared__ float s_out[32][33];   // [point][feat], padded

    const int tid   = threadIdx.x;
    const int lane  = tid & 31;
    const int warp  = tid >> 5;
    const int pbase = blockIdx.x * 32;

    if (tid < 96) {
        const int g = pbase * 3 + tid;
        s_c[tid] = (g < n_points * 3) ? coords[g] : 0.0f;
    }
    __syncthreads();

    // ---------------- hashed level (all 11 warps) ----------------
    {
        const int level = warp + NDENSE;
        const float x = s_c[lane*3+0], y = s_c[lane*3+1], z = s_c[lane*3+2];
        const float sc = c_scale[level];

        const float px = x*sc + 0.5f, py = y*sc + 0.5f, pz = z*sc + 0.5f;
        const float fx = floorf(px), fy = floorf(py), fz = floorf(pz);
        const float wx = px - fx,    wy = py - fy,    wz = pz - fz;
        const unsigned gx = (unsigned)fx, gy = (unsigned)fy, gz = (unsigned)fz;

        const unsigned hy0 = gy * PRIME2, hy1 = hy0 + PRIME2;
        const unsigned hz0 = gz * PRIME3, hz1 = hz0 + PRIME3;
        // j = (dy,dz): 0=(0,0) 1=(0,1) 2=(1,0) 3=(1,1); dx=0 -> v[j], dx=1 -> v[4+j]
        unsigned e[4];
        e[0] = (gx ^ hy0 ^ hz0) & TMASK;
        e[1] = (gx ^ hy0 ^ hz1) & TMASK;
        e[2] = (gx ^ hy1 ^ hz0) & TMASK;
        e[3] = (gx ^ hy1 ^ hz1) & TMASK;

        const float2* __restrict__ tbl = table + (size_t)level * (size_t)TSZ;
        float2 v[8];
        if (!(gx & 1u)) {
            // even gx: x-corner pair = entries {e&~1, e|1} -> one 16B load
            #pragma unroll
            for (int j = 0; j < 4; ++j) {
                const float4 q = __ldg(reinterpret_cast<const float4*>(tbl + (e[j] & ~1u)));
                const bool hi = (e[j] & 1u);
                v[j]     = hi ? make_float2(q.z, q.w) : make_float2(q.x, q.y);
                v[4 + j] = hi ? make_float2(q.x, q.y) : make_float2(q.z, q.w);
            }
        } else {
            const unsigned gx1 = gx + 1u;
            unsigned f[4];
            f[0] = (gx1 ^ hy0 ^ hz0) & TMASK;
            f[1] = (gx1 ^ hy0 ^ hz1) & TMASK;
            f[2] = (gx1 ^ hy1 ^ hz0) & TMASK;
            f[3] = (gx1 ^ hy1 ^ hz1) & TMASK;
            #pragma unroll
            for (int j = 0; j < 4; ++j) v[j]     = __ldg(tbl + e[j]);
            #pragma unroll
            for (int j = 0; j < 4; ++j) v[4 + j] = __ldg(tbl + f[j]);
        }

        const float ix = 1.0f - wx, iy = 1.0f - wy, iz = 1.0f - wz;
        const float a00 = ix*iy, a01 = ix*wy, a10 = wx*iy, a11 = wx*wy;
        const float w0 = a00*iz, w1 = a00*wz, w2 = a01*iz, w3 = a01*wz;
        const float w4 = a10*iz, w5 = a10*wz, w6 = a11*iz, w7 = a11*wz;

        float f0 = w0*v[0].x;  float f1 = w0*v[0].y;
        f0 += w1*v[1].x;       f1 += w1*v[1].y;
        f0 += w2*v[2].x;       f1 += w2*v[2].y;
        f0 += w3*v[3].x;       f1 += w3*v[3].y;
        f0 += w4*v[4].x;       f1 += w4*v[4].y;
        f0 += w5*v[5].x;       f1 += w5*v[5].y;
        f0 += w6*v[6].x;       f1 += w6*v[6].y;
        f0 += w7*v[7].x;       f1 += w7*v[7].y;

        s_out[lane][2*level + 0] = f0;
        s_out[lane][2*level + 1] = f1;
    }

    // ---------------- dense level (warps 0..4 only) ----------------
    if (warp < NDENSE) {
        const int level = warp;
        const float    sc   = c_scale[level];
        const unsigned res  = c_res[level];
        const unsigned res2 = c_res2[level];
        const unsigned coff = c_coff[level];
        const int q = lane >> 2;                  // 0..7 point-in-subgroup
        const int k = lane & 3;                   // chunk: dx=k>>1, dy=k&1

        #pragma unroll
        for (int it = 0; it < 4; ++it) {
            const int pt = it * 8 + q;            // 0..31
            const float x = s_c[pt*3+0], y = s_c[pt*3+1], z = s_c[pt*3+2];
            const float px = x*sc + 0.5f, py = y*sc + 0.5f, pz = z*sc + 0.5f;
            const float fx = floorf(px), fy = floorf(py), fz = floorf(pz);
            const float wx = px - fx,    wy = py - fy,    wz = pz - fz;
            const unsigned gx = (unsigned)fx, gy = (unsigned)fy, gz = (unsigned)fz;

            const unsigned cell = coff + gx + gy*res + gz*res2;
            const float4 ch = __ldg(&g_cells[(size_t)cell * 4 + k]);  // 4 lanes: 1 line

            const float wdx = (k & 2) ? wx : 1.0f - wx;
            const float wdy = (k & 1) ? wy : 1.0f - wy;
            const float izz = 1.0f - wz;
            const float s   = wdx * wdy;
            float f0 = s * (izz*ch.x + wz*ch.z);
            float f1 = s * (izz*ch.y + wz*ch.w);

            f0 += __shfl_xor_sync(0xffffffffu, f0, 1);
            f1 += __shfl_xor_sync(0xffffffffu, f1, 1);
            f0 += __shfl_xor_sync(0xffffffffu, f0, 2);
            f1 += __shfl_xor_sync(0xffffffffu, f1, 2);

            if (k == 0) {
                s_out[pt][2*level + 0] = f0;
                s_out[pt][2*level + 1] = f1;
            }
        }
    }
    __syncthreads();

    // Coalesced writeback: 512 float2 = 4KB contiguous per block, strided
    // over 352 threads.
    #pragma unroll
    for (int idx = tid; idx < 512; idx += 352) {
        const int pp = idx >> 4;
        const int c  = (idx & 15) * 2;
        const int gp = pbase + pp;
        if (gp < n_points) {
            const float a = s_out[pp][c];
            const float b = s_out[pp][c + 1];
            float2* o = reinterpret_cast<float2*>(out + (size_t)gp * 32 + c);
            *o = make_float2(a, b);
        }
    }
}

extern "C" void kernel_launch(void* const* d_in, const int* in_sizes, int n_in,
                              void* d_out, int out_size) {
    const float*  coords = (const float*)d_in[0];   // [N, 3] f32
    const float2* table  = (const float2*)d_in[1];  // [16, 2^19, 2] f32
    float*        out    = (float*)d_out;           // [N, 32] f32
    const int n_points = in_sizes[0] / 3;

    hg_repack<<<(TOTAL_CELLS + 255) / 256, 256>>>(table);
    const int blocks = (n_points + 31) / 32;
    hg_encode<<<blocks, 352>>>(coords, table, out, n_points);
}

// round 6
// speedup vs baseline: 1.5295x; 1.1509x over previous
#include <cuda_runtime.h>
#include <stdint.h>

// ---------------------------------------------------------------------------
// tcnn HashGrid encode: coords [N,3] in [0,1], table [16, 2^19, 2] f32.
// Output [N, 32] f32. Levels 0-4 dense, 5-15 spatial-hashed.
//
// R6: balance dense work across ALL warps. R5 folded the 5 dense levels into
// warps 0..4 only (those warps: ~7 wavefront-units/pt vs 6 for warps 5..10;
// block time = max). Now the 640 dense quad-tasks per block (5 lvls x 32 pts
// x 4 chunks) are spread flat over all 352 lanes: task tid for everyone,
// task tid+352 for lanes<288 (warps 0..8, whole warps -> quad shfl intact).
// Hashed path: proven divergent even/odd x-pair merge (PRIME_x==1).
// ---------------------------------------------------------------------------

namespace {
constexpr int      NLV    = 16;
constexpr int      NDENSE = 5;
constexpr int      NHASH  = 11;
constexpr unsigned TSZ    = 1u << 19;
constexpr unsigned TMASK  = TSZ - 1u;
constexpr unsigned PRIME2 = 2654435761u;
constexpr unsigned PRIME3 = 805459861u;

constexpr double spow(int l) {
    double v = 1.0;
    for (int i = 0; i < l; ++i) v *= 1.4472692012786865;
    return v;
}
constexpr double scaled(int l) { return 16.0 * spow(l) - 1.0; }
constexpr unsigned resd(int l) {
    double sc = scaled(l);
    unsigned f = (unsigned)sc;
    return f + (((double)f < sc) ? 1u : 0u) + 1u;
}
constexpr unsigned cells_below(int l) {
    unsigned o = 0;
    for (int i = 0; i < l; ++i) o += resd(i) * resd(i) * resd(i);
    return o;
}
constexpr unsigned TOTAL_CELLS = cells_below(NDENSE);
static_assert(resd(0) == 16 && resd(4) == 71, "dense res sanity");
static_assert((unsigned long long)resd(4)*resd(4)*resd(4) <= TSZ, "lvl4 dense");
static_assert((unsigned long long)resd(5)*resd(5)*resd(5) >  TSZ, "lvl5 hashed");
static_assert(TOTAL_CELLS == 532784u, "cell count");
}

__constant__ float    c_scale[NLV] = {
    (float)scaled(0),(float)scaled(1),(float)scaled(2),(float)scaled(3),
    (float)scaled(4),(float)scaled(5),(float)scaled(6),(float)scaled(7),
    (float)scaled(8),(float)scaled(9),(float)scaled(10),(float)scaled(11),
    (float)scaled(12),(float)scaled(13),(float)scaled(14),(float)scaled(15)};
__constant__ unsigned c_res[NDENSE]  = {resd(0),resd(1),resd(2),resd(3),resd(4)};
__constant__ unsigned c_res2[NDENSE] = {resd(0)*resd(0),resd(1)*resd(1),
    resd(2)*resd(2),resd(3)*resd(3),resd(4)*resd(4)};
__constant__ unsigned c_coff[NDENSE] = {cells_below(0),cells_below(1),
    cells_below(2),cells_below(3),cells_below(4)};

__device__ __align__(128) float4 g_cells[(size_t)TOTAL_CELLS * 4];

// --- repack dense levels: cell (gx,gy,gz) -> 4 float4 = 8 corners (64B).
// chunk k: dx=k>>1, dy=k&1; dz=0 in .xy, dz=1 in .zw.
__global__ void hg_repack(const float2* __restrict__ table) {
    unsigned cid = blockIdx.x * blockDim.x + threadIdx.x;
    if (cid >= TOTAL_CELLS) return;

    int l = 0;
    #pragma unroll
    for (int i = 1; i < NDENSE; ++i) if (cid >= c_coff[i]) l = i;
    const unsigned res = c_res[l], res2 = c_res2[l];
    const unsigned local = cid - c_coff[l];
    const unsigned gz  = local / res2;
    const unsigned rem = local - gz * res2;
    const unsigned gy  = rem / res;
    const unsigned gx  = rem - gy * res;

    const unsigned R1  = res - 1u;
    const unsigned cx0 = gx,          cx1 = min(gx + 1u, R1);
    const unsigned cy0 = gy * res,    cy1 = min(gy + 1u, R1) * res;
    const unsigned cz0 = gz * res2,   cz1 = min(gz + 1u, R1) * res2;

    const float2* __restrict__ tbl = table + (size_t)l * (size_t)TSZ;
    float4* dst = &g_cells[(size_t)cid * 4];
    { float2 a = tbl[cx0+cy0+cz0], b = tbl[cx0+cy0+cz1]; dst[0]=make_float4(a.x,a.y,b.x,b.y); }
    { float2 a = tbl[cx0+cy1+cz0], b = tbl[cx0+cy1+cz1]; dst[1]=make_float4(a.x,a.y,b.x,b.y); }
    { float2 a = tbl[cx1+cy0+cz0], b = tbl[cx1+cy0+cz1]; dst[2]=make_float4(a.x,a.y,b.x,b.y); }
    { float2 a = tbl[cx1+cy1+cz0], b = tbl[cx1+cy1+cz1]; dst[3]=make_float4(a.x,a.y,b.x,b.y); }
}

// --- main encode. Block = 352 threads = 11 warps, 32 points per block.
// Warp w: hashed level w+5 (lane = point). Dense: 640 quad-tasks spread
// flat over all lanes (1 task each, +1 more for lanes < 288).
__global__ __launch_bounds__(352, 5) void hg_encode(
    const float*  __restrict__ coords,
    const float2* __restrict__ table,
    float*        __restrict__ out,
    int n_points)
{
    __shared__ float s_c[96];         // 32 points x 3 coords
    __shared__ float s_out[32][33];   // [point][feat], padded

    const int tid   = threadIdx.x;
    const int lane  = tid & 31;
    const int warp  = tid >> 5;
    const int pbase = blockIdx.x * 32;

    if (tid < 96) {
        const int g = pbase * 3 + tid;
        s_c[tid] = (g < n_points * 3) ? coords[g] : 0.0f;
    }
    __syncthreads();

    // ---------------- hashed level (all 11 warps) ----------------
    {
        const int level = warp + NDENSE;
        const float x = s_c[lane*3+0], y = s_c[lane*3+1], z = s_c[lane*3+2];
        const float sc = c_scale[level];

        const float px = x*sc + 0.5f, py = y*sc + 0.5f, pz = z*sc + 0.5f;
        const float fx = floorf(px), fy = floorf(py), fz = floorf(pz);
        const float wx = px - fx,    wy = py - fy,    wz = pz - fz;
        const unsigned gx = (unsigned)fx, gy = (unsigned)fy, gz = (unsigned)fz;

        const unsigned hy0 = gy * PRIME2, hy1 = hy0 + PRIME2;
        const unsigned hz0 = gz * PRIME3, hz1 = hz0 + PRIME3;
        // j = (dy,dz): 0=(0,0) 1=(0,1) 2=(1,0) 3=(1,1); dx=0 -> v[j], dx=1 -> v[4+j]
        unsigned e[4];
        e[0] = (gx ^ hy0 ^ hz0) & TMASK;
        e[1] = (gx ^ hy0 ^ hz1) & TMASK;
        e[2] = (gx ^ hy1 ^ hz0) & TMASK;
        e[3] = (gx ^ hy1 ^ hz1) & TMASK;

        const float2* __restrict__ tbl = table + (size_t)level * (size_t)TSZ;
        float2 v[8];
        if (!(gx & 1u)) {
            // even gx: x-corner pair = entries {e&~1, e|1} -> one 16B load
            #pragma unroll
            for (int j = 0; j < 4; ++j) {
                const float4 q = __ldg(reinterpret_cast<const float4*>(tbl + (e[j] & ~1u)));
                const bool hi = (e[j] & 1u);
                v[j]     = hi ? make_float2(q.z, q.w) : make_float2(q.x, q.y);
                v[4 + j] = hi ? make_float2(q.x, q.y) : make_float2(q.z, q.w);
            }
        } else {
            const unsigned gx1 = gx + 1u;
            unsigned f[4];
            f[0] = (gx1 ^ hy0 ^ hz0) & TMASK;
            f[1] = (gx1 ^ hy0 ^ hz1) & TMASK;
            f[2] = (gx1 ^ hy1 ^ hz0) & TMASK;
            f[3] = (gx1 ^ hy1 ^ hz1) & TMASK;
            #pragma unroll
            for (int j = 0; j < 4; ++j) v[j]     = __ldg(tbl + e[j]);
            #pragma unroll
            for (int j = 0; j < 4; ++j) v[4 + j] = __ldg(tbl + f[j]);
        }

        const float ix = 1.0f - wx, iy = 1.0f - wy, iz = 1.0f - wz;
        const float a00 = ix*iy, a01 = ix*wy, a10 = wx*iy, a11 = wx*wy;
        const float w0 = a00*iz, w1 = a00*wz, w2 = a01*iz, w3 = a01*wz;
        const float w4 = a10*iz, w5 = a10*wz, w6 = a11*iz, w7 = a11*wz;

        float f0 = w0*v[0].x;  float f1 = w0*v[0].y;
        f0 += w1*v[1].x;       f1 += w1*v[1].y;
        f0 += w2*v[2].x;       f1 += w2*v[2].y;
        f0 += w3*v[3].x;       f1 += w3*v[3].y;
        f0 += w4*v[4].x;       f1 += w4*v[4].y;
        f0 += w5*v[5].x;       f1 += w5*v[5].y;
        f0 += w6*v[6].x;       f1 += w6*v[6].y;
        f0 += w7*v[7].x;       f1 += w7*v[7].y;

        s_out[lane][2*level + 0] = f0;
        s_out[lane][2*level + 1] = f1;
    }

    // ---------------- dense levels: 640 quad-tasks over all lanes ----------
    // task d: level = d>>7 (128 tasks/level), pt = (d>>2)&31, chunk k = d&3.
    // Quads (4 consecutive d) stay within one warp: 352 % 4 == 0.
    #pragma unroll
    for (int pass = 0; pass < 2; ++pass) {
        const int d = tid + pass * 352;
        if (d < 640) {                       // pass 0: all; pass 1: warps 0..8
            const int lvl = d >> 7;
            const int pt  = (d >> 2) & 31;
            const int k   = d & 3;           // dx=k>>1, dy=k&1

            const float    sc   = c_scale[lvl];
            const unsigned res  = c_res[lvl];
            const unsigned res2 = c_res2[lvl];
            const unsigned coff = c_coff[lvl];

            const float x = s_c[pt*3+0], y = s_c[pt*3+1], z = s_c[pt*3+2];
            const float px = x*sc + 0.5f, py = y*sc + 0.5f, pz = z*sc + 0.5f;
            const float fx = floorf(px), fy = floorf(py), fz = floorf(pz);
            const float wx = px - fx,    wy = py - fy,    wz = pz - fz;
            const unsigned gx = (unsigned)fx, gy = (unsigned)fy, gz = (unsigned)fz;

            const unsigned cell = coff + gx + gy*res + gz*res2;
            const float4 ch = __ldg(&g_cells[(size_t)cell * 4 + k]);  // quad: 1 line

            const float wdx = (k & 2) ? wx : 1.0f - wx;
            const float wdy = (k & 1) ? wy : 1.0f - wy;
            const float izz = 1.0f - wz;
            const float s   = wdx * wdy;
            float f0 = s * (izz*ch.x + wz*ch.z);
            float f1 = s * (izz*ch.y + wz*ch.w);

            f0 += __shfl_xor_sync(0xffffffffu, f0, 1);
            f1 += __shfl_xor_sync(0xffffffffu, f1, 1);
            f0 += __shfl_xor_sync(0xffffffffu, f0, 2);
            f1 += __shfl_xor_sync(0xffffffffu, f1, 2);

            if (k == 0) {
                s_out[pt][2*lvl + 0] = f0;
                s_out[pt][2*lvl + 1] = f1;
            }
        }
    }
    __syncthreads();

    // Coalesced writeback: 512 float2 = 4KB contiguous per block, strided
    // over 352 threads.
    #pragma unroll
    for (int idx = tid; idx < 512; idx += 352) {
        const int pp = idx >> 4;
        const int c  = (idx & 15) * 2;
        const int gp = pbase + pp;
        if (gp < n_points) {
            const float a = s_out[pp][c];
            const float b = s_out[pp][c + 1];
            float2* o = reinterpret_cast<float2*>(out + (size_t)gp * 32 + c);
            *o = make_float2(a, b);
        }
    }
}

extern "C" void kernel_launch(void* const* d_in, const int* in_sizes, int n_in,
                              void* d_out, int out_size) {
    const float*  coords = (const float*)d_in[0];   // [N, 3] f32
    const float2* table  = (const float2*)d_in[1];  // [16, 2^19, 2] f32
    float*        out    = (float*)d_out;           // [N, 32] f32
    const int n_points = in_sizes[0] / 3;

    hg_repack<<<(TOTAL_CELLS + 255) / 256, 256>>>(table);
    const int blocks = (n_points + 31) / 32;
    hg_encode<<<blocks, 352>>>(coords, table, out, n_points);
}

// round 7
// speedup vs baseline: 1.6065x; 1.0504x over previous
#include <cuda_runtime.h>
#include <stdint.h>

// ---------------------------------------------------------------------------
// tcnn HashGrid encode: coords [N,3] in [0,1], table [16, 2^19, 2] f32.
// Output [N, 32] f32. Levels 0-4 dense, 5-15 spatial-hashed.
//
// R7: 64 points per block (2 groups of 32 per warp). Halves the barrier and
// block-launch overhead per point and averages each warp's even/odd gx
// parity mix over 2x the loads (block exit is set by the slowest warp).
// Structure otherwise = R6: 11 warps, warp w owns hashed level w+5;
// 1280 dense quad-tasks spread flat over all lanes (repacked 64B cell
// records, quad-lane LDG.128); padded smem staging + coalesced writeback.
// ---------------------------------------------------------------------------

namespace {
constexpr int      NLV    = 16;
constexpr int      NDENSE = 5;
constexpr int      NHASH  = 11;
constexpr unsigned TSZ    = 1u << 19;
constexpr unsigned TMASK  = TSZ - 1u;
constexpr unsigned PRIME2 = 2654435761u;
constexpr unsigned PRIME3 = 805459861u;
constexpr int      PTS    = 64;     // points per block

constexpr double spow(int l) {
    double v = 1.0;
    for (int i = 0; i < l; ++i) v *= 1.4472692012786865;
    return v;
}
constexpr double scaled(int l) { return 16.0 * spow(l) - 1.0; }
constexpr unsigned resd(int l) {
    double sc = scaled(l);
    unsigned f = (unsigned)sc;
    return f + (((double)f < sc) ? 1u : 0u) + 1u;
}
constexpr unsigned cells_below(int l) {
    unsigned o = 0;
    for (int i = 0; i < l; ++i) o += resd(i) * resd(i) * resd(i);
    return o;
}
constexpr unsigned TOTAL_CELLS = cells_below(NDENSE);
static_assert(resd(0) == 16 && resd(4) == 71, "dense res sanity");
static_assert((unsigned long long)resd(4)*resd(4)*resd(4) <= TSZ, "lvl4 dense");
static_assert((unsigned long long)resd(5)*resd(5)*resd(5) >  TSZ, "lvl5 hashed");
static_assert(TOTAL_CELLS == 532784u, "cell count");
}

__constant__ float    c_scale[NLV] = {
    (float)scaled(0),(float)scaled(1),(float)scaled(2),(float)scaled(3),
    (float)scaled(4),(float)scaled(5),(float)scaled(6),(float)scaled(7),
    (float)scaled(8),(float)scaled(9),(float)scaled(10),(float)scaled(11),
    (float)scaled(12),(float)scaled(13),(float)scaled(14),(float)scaled(15)};
__constant__ unsigned c_res[NDENSE]  = {resd(0),resd(1),resd(2),resd(3),resd(4)};
__constant__ unsigned c_res2[NDENSE] = {resd(0)*resd(0),resd(1)*resd(1),
    resd(2)*resd(2),resd(3)*resd(3),resd(4)*resd(4)};
__constant__ unsigned c_coff[NDENSE] = {cells_below(0),cells_below(1),
    cells_below(2),cells_below(3),cells_below(4)};

__device__ __align__(128) float4 g_cells[(size_t)TOTAL_CELLS * 4];

// --- repack dense levels: cell (gx,gy,gz) -> 4 float4 = 8 corners (64B).
// chunk k: dx=k>>1, dy=k&1; dz=0 in .xy, dz=1 in .zw.
__global__ void hg_repack(const float2* __restrict__ table) {
    unsigned cid = blockIdx.x * blockDim.x + threadIdx.x;
    if (cid >= TOTAL_CELLS) return;

    int l = 0;
    #pragma unroll
    for (int i = 1; i < NDENSE; ++i) if (cid >= c_coff[i]) l = i;
    const unsigned res = c_res[l], res2 = c_res2[l];
    const unsigned local = cid - c_coff[l];
    const unsigned gz  = local / res2;
    const unsigned rem = local - gz * res2;
    const unsigned gy  = rem / res;
    const unsigned gx  = rem - gy * res;

    const unsigned R1  = res - 1u;
    const unsigned cx0 = gx,          cx1 = min(gx + 1u, R1);
    const unsigned cy0 = gy * res,    cy1 = min(gy + 1u, R1) * res;
    const unsigned cz0 = gz * res2,   cz1 = min(gz + 1u, R1) * res2;

    const float2* __restrict__ tbl = table + (size_t)l * (size_t)TSZ;
    float4* dst = &g_cells[(size_t)cid * 4];
    { float2 a = tbl[cx0+cy0+cz0], b = tbl[cx0+cy0+cz1]; dst[0]=make_float4(a.x,a.y,b.x,b.y); }
    { float2 a = tbl[cx0+cy1+cz0], b = tbl[cx0+cy1+cz1]; dst[1]=make_float4(a.x,a.y,b.x,b.y); }
    { float2 a = tbl[cx1+cy0+cz0], b = tbl[cx1+cy0+cz1]; dst[2]=make_float4(a.x,a.y,b.x,b.y); }
    { float2 a = tbl[cx1+cy1+cz0], b = tbl[cx1+cy1+cz1]; dst[3]=make_float4(a.x,a.y,b.x,b.y); }
}

// --- main encode. Block = 352 threads = 11 warps, 64 points per block.
// Warp w: hashed level w+5 for point groups {lane, lane+32}.
// Dense: 1280 quad-tasks (5 lvl x 64 pt x 4 chunk) flat over all lanes.
__global__ __launch_bounds__(352, 5) void hg_encode(
    const float*  __restrict__ coords,
    const float2* __restrict__ table,
    float*        __restrict__ out,
    int n_points)
{
    __shared__ float s_c[PTS * 3];        // 64 points x 3 coords
    __shared__ float s_out[PTS][33];      // [point][feat], padded

    const int tid   = threadIdx.x;
    const int lane  = tid & 31;
    const int warp  = tid >> 5;
    const int pbase = blockIdx.x * PTS;

    if (tid < PTS * 3) {
        const int g = pbase * 3 + tid;
        s_c[tid] = (g < n_points * 3) ? coords[g] : 0.0f;
    }
    __syncthreads();

    // ---------------- hashed level (all 11 warps, 2 point groups) ----------
    {
        const int level = warp + NDENSE;
        const float sc = c_scale[level];
        const float2* __restrict__ tbl = table + (size_t)level * (size_t)TSZ;

        #pragma unroll
        for (int grp = 0; grp < 2; ++grp) {
            const int pt = grp * 32 + lane;
            const float x = s_c[pt*3+0], y = s_c[pt*3+1], z = s_c[pt*3+2];

            const float px = x*sc + 0.5f, py = y*sc + 0.5f, pz = z*sc + 0.5f;
            const float fx = floorf(px), fy = floorf(py), fz = floorf(pz);
            const float wx = px - fx,    wy = py - fy,    wz = pz - fz;
            const unsigned gx = (unsigned)fx, gy = (unsigned)fy, gz = (unsigned)fz;

            const unsigned hy0 = gy * PRIME2, hy1 = hy0 + PRIME2;
            const unsigned hz0 = gz * PRIME3, hz1 = hz0 + PRIME3;
            // j = (dy,dz): 0=(0,0) 1=(0,1) 2=(1,0) 3=(1,1); dx=0->v[j], dx=1->v[4+j]
            unsigned e[4];
            e[0] = (gx ^ hy0 ^ hz0) & TMASK;
            e[1] = (gx ^ hy0 ^ hz1) & TMASK;
            e[2] = (gx ^ hy1 ^ hz0) & TMASK;
            e[3] = (gx ^ hy1 ^ hz1) & TMASK;

            float2 v[8];
            if (!(gx & 1u)) {
                // even gx: x-corner pair = entries {e&~1, e|1} -> one 16B load
                #pragma unroll
                for (int j = 0; j < 4; ++j) {
                    const float4 q = __ldg(reinterpret_cast<const float4*>(tbl + (e[j] & ~1u)));
                    const bool hi = (e[j] & 1u);
                    v[j]     = hi ? make_float2(q.z, q.w) : make_float2(q.x, q.y);
                    v[4 + j] = hi ? make_float2(q.x, q.y) : make_float2(q.z, q.w);
                }
            } else {
                const unsigned gx1 = gx + 1u;
                unsigned f[4];
                f[0] = (gx1 ^ hy0 ^ hz0) & TMASK;
                f[1] = (gx1 ^ hy0 ^ hz1) & TMASK;
                f[2] = (gx1 ^ hy1 ^ hz0) & TMASK;
                f[3] = (gx1 ^ hy1 ^ hz1) & TMASK;
                #pragma unroll
                for (int j = 0; j < 4; ++j) v[j]     = __ldg(tbl + e[j]);
                #pragma unroll
                for (int j = 0; j < 4; ++j) v[4 + j] = __ldg(tbl + f[j]);
            }

            const float ix = 1.0f - wx, iy = 1.0f - wy, iz = 1.0f - wz;
            const float a00 = ix*iy, a01 = ix*wy, a10 = wx*iy, a11 = wx*wy;
            const float w0 = a00*iz, w1 = a00*wz, w2 = a01*iz, w3 = a01*wz;
            const float w4 = a10*iz, w5 = a10*wz, w6 = a11*iz, w7 = a11*wz;

            float f0 = w0*v[0].x;  float f1 = w0*v[0].y;
            f0 += w1*v[1].x;       f1 += w1*v[1].y;
            f0 += w2*v[2].x;       f1 += w2*v[2].y;
            f0 += w3*v[3].x;       f1 += w3*v[3].y;
            f0 += w4*v[4].x;       f1 += w4*v[4].y;
            f0 += w5*v[5].x;       f1 += w5*v[5].y;
            f0 += w6*v[6].x;       f1 += w6*v[6].y;
            f0 += w7*v[7].x;       f1 += w7*v[7].y;

            s_out[pt][2*level + 0] = f0;
            s_out[pt][2*level + 1] = f1;
        }
    }

    // ---------------- dense levels: 1280 quad-tasks over all lanes ---------
    // task d: level = d>>8 (256 tasks/level), pt = (d>>2)&63, chunk k = d&3.
    // Quads (4 consecutive d) stay within one warp: 352 % 4 == 0; last pass
    // covers lanes < 224 = 7 whole warps.
    #pragma unroll
    for (int pass = 0; pass < 4; ++pass) {
        const int d = tid + pass * 352;
        if (d < 1280) {
            const int lvl = d >> 8;
            const int pt  = (d >> 2) & 63;
            const int k   = d & 3;           // dx=k>>1, dy=k&1

            const float    sc   = c_scale[lvl];
            const unsigned res  = c_res[lvl];
            const unsigned res2 = c_res2[lvl];
            const unsigned coff = c_coff[lvl];

            const float x = s_c[pt*3+0], y = s_c[pt*3+1], z = s_c[pt*3+2];
            const float px = x*sc + 0.5f, py = y*sc + 0.5f, pz = z*sc + 0.5f;
            const float fx = floorf(px), fy = floorf(py), fz = floorf(pz);
            const float wx = px - fx,    wy = py - fy,    wz = pz - fz;
            const unsigned gx = (unsigned)fx, gy = (unsigned)fy, gz = (unsigned)fz;

            const unsigned cell = coff + gx + gy*res + gz*res2;
            const float4 ch = __ldg(&g_cells[(size_t)cell * 4 + k]);  // quad: 1 line

            const float wdx = (k & 2) ? wx : 1.0f - wx;
            const float wdy = (k & 1) ? wy : 1.0f - wy;
            const float izz = 1.0f - wz;
            const float s   = wdx * wdy;
            float f0 = s * (izz*ch.x + wz*ch.z);
            float f1 = s * (izz*ch.y + wz*ch.w);

            f0 += __shfl_xor_sync(0xffffffffu, f0, 1);
            f1 += __shfl_xor_sync(0xffffffffu, f1, 1);
            f0 += __shfl_xor_sync(0xffffffffu, f0, 2);
            f1 += __shfl_xor_sync(0xffffffffu, f1, 2);

            if (k == 0) {
                s_out[pt][2*lvl + 0] = f0;
                s_out[pt][2*lvl + 1] = f1;
            }
        }
    }
    __syncthreads();

    // Coalesced writeback: 1024 float2 = 8KB contiguous per block, strided
    // over 352 threads.
    #pragma unroll
    for (int idx = tid; idx < PTS * 16; idx += 352) {
        const int pp = idx >> 4;
        const int c  = (idx & 15) * 2;
        const int gp = pbase + pp;
        if (gp < n_points) {
            const float a = s_out[pp][c];
            const float b = s_out[pp][c + 1];
            float2* o = reinterpret_cast<float2*>(out + (size_t)gp * 32 + c);
            *o = make_float2(a, b);
        }
    }
}

extern "C" void kernel_launch(void* const* d_in, const int* in_sizes, int n_in,
                              void* d_out, int out_size) {
    const float*  coords = (const float*)d_in[0];   // [N, 3] f32
    const float2* table  = (const float2*)d_in[1];  // [16, 2^19, 2] f32
    float*        out    = (float*)d_out;           // [N, 32] f32
    const int n_points = in_sizes[0] / 3;

    hg_repack<<<(TOTAL_CELLS + 255) / 256, 256>>>(table);
    const int blocks = (n_points + PTS - 1) / PTS;
    hg_encode<<<blocks, 352>>>(coords, table, out, n_points);
}